// round 6
// baseline (speedup 1.0000x reference)
#include <cuda_runtime.h>

// Cost volume s2: B=4, C=32, H=W=256, D=9, 8 groups of 4 channels.
// y-offset 0 -> 1D lerp in x; res span 0.8 < 1 px -> 3 taps/side cover all d.
// Abs-form hat lerp: w = P1 + t*S + |t|*Dd  (S=(P2-P0)/2, Dd=(P2+P0)/2-P1).
// cost = (1/18) * ( Sum(wl^2+wr^2) + Sum F^2 - Sum wl*wr - Sum F*(wl+wr) ).
// ONE THREAD = ONE (b, group, pixel): single 28-LDG burst per thread (paid
// once, hidden by warp streaming) instead of 8 sequential bursts per thread.

typedef unsigned long long u64;

constexpr int Wd = 256, Cn = 32, Bn = 4, Dn = 9, Gn = 8, CPG = 4;
constexpr int HW = 256 * 256;

__device__ __forceinline__ u64 pk(float a, float b) {
    u64 r; asm("mov.b64 %0, {%1, %2};" : "=l"(r) : "f"(a), "f"(b)); return r;
}
__device__ __forceinline__ void upk(float& a, float& b, u64 v) {
    asm("mov.b64 {%0, %1}, %2;" : "=f"(a), "=f"(b) : "l"(v));
}
__device__ __forceinline__ u64 ffma2(u64 a, u64 b, u64 c) {
    u64 d; asm("fma.rn.f32x2 %0, %1, %2, %3;" : "=l"(d) : "l"(a), "l"(b), "l"(c));
    return d;
}
__device__ __forceinline__ u64 add2(u64 a, u64 b) {
    u64 d; asm("add.rn.f32x2 %0, %1, %2;" : "=l"(d) : "l"(a), "l"(b));
    return d;
}

__global__ __launch_bounds__(256) void cost_volume_kernel(
    const float* __restrict__ fref,
    const float* __restrict__ fls,
    const float* __restrict__ frs,
    const float* __restrict__ dinit,
    float* __restrict__ out)
{
    // grid = B*G*(HW/256); block handles 256 consecutive pixels of one (b,g).
    const int bg = blockIdx.x >> 8;           // 0..31
    const int g  = bg & 7;
    const int b  = bg >> 3;
    const int hw = ((blockIdx.x & 255) << 8) + threadIdx.x;
    const int w  = hw & (Wd - 1);

    const float disp = __ldg(dinit + b * HW + hw);
    const float wf = (float)w;

    // Left taps at n_l..n_l+2, n_l = floor(x_l at d=0); x_l increases with d.
    const float xl0 = wf + disp - 0.4f;
    const float fll = floorf(xl0);
    const int   n_l = (int)fll;
    const float tl0 = xl0 - fll - 1.0f;            // t_l at d=0, in [-1, 0)

    // Right taps at n_r..n_r+2, n_r = floor(x_r at d=8); x_r decreases with d.
    const float xr0 = wf - disp + 0.4f;            // x_r at d=0 (max over d)
    const float flr = floorf(xr0 - 0.8f);          // floor of min x_r (d=8)
    const int   n_r = (int)flr;
    const float tr0 = xr0 - flr - 1.0f;            // t_r at d=0

    const u64 t02   = pk(tl0, tr0);
    const u64 step2 = pk(0.1f, -0.1f);
    const u64 amask = 0x7FFFFFFF7FFFFFFFull;

    const bool vL0 = (unsigned)(n_l)     < (unsigned)Wd;
    const bool vL1 = (unsigned)(n_l + 1) < (unsigned)Wd;
    const bool vL2 = (unsigned)(n_l + 2) < (unsigned)Wd;
    const bool vR0 = (unsigned)(n_r)     < (unsigned)Wd;
    const bool vR1 = (unsigned)(n_r + 1) < (unsigned)Wd;
    const bool vR2 = (unsigned)(n_r + 2) < (unsigned)Wd;

    const int rowbase0 = b * Cn * HW + (hw - w) + g * CPG * HW;  // 1st channel row
    float* outp = out + b * (Gn * Dn * HW) + g * Dn * HW + hw;

    const float c18 = 1.0f / 18.0f;

    // Single load burst: all 28 taps for this (b,g,pixel).
    u64 P1[CPG], Sv[CPG], Dd[CPG], Fb[CPG];
    float sFg = 0.0f;

    #pragma unroll
    for (int ci = 0; ci < CPG; ci++) {
        const int rb = rowbase0 + ci * HW;
        const float* pl = fls + rb;
        const float* pr = frs + rb;

        const float L0 = vL0 ? __ldg(pl + n_l)     : 0.0f;
        const float L1 = vL1 ? __ldg(pl + n_l + 1) : 0.0f;
        const float L2 = vL2 ? __ldg(pl + n_l + 2) : 0.0f;
        const float R0 = vR0 ? __ldg(pr + n_r)     : 0.0f;
        const float R1 = vR1 ? __ldg(pr + n_r + 1) : 0.0f;
        const float R2 = vR2 ? __ldg(pr + n_r + 2) : 0.0f;
        const float F  = __ldg(fref + rb + w);

        P1[ci] = pk(L1, R1);
        Sv[ci] = pk(0.5f * (L2 - L0), 0.5f * (R2 - R0));
        Dd[ci] = pk(fmaf(0.5f, L2 + L0, -L1), fmaf(0.5f, R2 + R0, -R1));
        Fb[ci] = pk(F, F);
        sFg = fmaf(F, F, sFg);
    }

    u64 t2 = t02;
    #pragma unroll
    for (int d = 0; d < 9; d++) {
        const u64 at2 = t2 & amask;                // (|t_l|, |t_r|)

        u64 acc2 = 0ull, accF = 0ull;
        float ax = 0.0f;
        #pragma unroll
        for (int ci = 0; ci < CPG; ci++) {
            const u64 lw = ffma2(t2, Sv[ci],
                           ffma2(at2, Dd[ci], P1[ci]));
            acc2 = ffma2(lw, lw, acc2);            // (S wl^2, S wr^2)
            accF = ffma2(Fb[ci], lw, accF);        // (S F wl, S F wr)
            float wl, wr; upk(wl, wr, lw);
            ax = fmaf(wl, wr, ax);                 // S wl*wr
        }
        t2 = add2(t2, step2);

        float a2l, a2r; upk(a2l, a2r, acc2);
        float aFl, aFr; upk(aFl, aFr, accF);
        const float hq = (a2l + a2r) + (sFg - ax);
        const float hf = aFl + aFr;
        const float cost = (hq - hf) * c18;
        __stcg(outp + d * HW, cost);
    }
}

extern "C" void kernel_launch(void* const* d_in, const int* in_sizes, int n_in,
                              void* d_out, int out_size)
{
    const float* fref  = (const float*)d_in[0];
    const float* fls   = (const float*)d_in[1];
    const float* frs   = (const float*)d_in[2];
    const float* dinit = (const float*)d_in[3];
    float* out = (float*)d_out;

    // B * Gn * HW / 256 threads-per-block = 4*8*65536/256 = 8192 blocks
    cost_volume_kernel<<<Bn * Gn * (HW / 256), 256>>>(fref, fls, frs, dinit, out);
}

// round 7
// speedup vs baseline: 1.1859x; 1.1859x over previous
#include <cuda_runtime.h>

// Cost volume s2: B=4, C=32, H=W=256, D=9, 8 groups of 4 channels.
// y-offset 0 -> 1D lerp in x; res span 0.8 < 1 px -> 3 taps/side cover all d.
// Abs-form hat lerp: w = P1 + t*S + |t|*Dd  (S=(P2-P0)/2, Dd=(P2+P0)/2-P1).
// cost = (1/18) * ( Sum(wl^2+wr^2) + Sum F^2 - Sum wl*wr - Sum F*(wl+wr) ).
// Block = one (b, row h, group g). Rows staged in SMEM via coalesced float4
// loads (each element read once); taps gathered via conflict-free LDS.
// Zero halo in SMEM implements the zero-padding -> no validity predicates.

typedef unsigned long long u64;

constexpr int Wd = 256, Cn = 32, Bn = 4, Dn = 9, Gn = 8, CPG = 4;
constexpr int HW = 256 * 256;
constexpr int RW = 268;          // padded SMEM row: 4 halo + 256 + 8 halo

__device__ __forceinline__ u64 pk(float a, float b) {
    u64 r; asm("mov.b64 %0, {%1, %2};" : "=l"(r) : "f"(a), "f"(b)); return r;
}
__device__ __forceinline__ void upk(float& a, float& b, u64 v) {
    asm("mov.b64 {%0, %1}, %2;" : "=f"(a), "=f"(b) : "l"(v));
}
__device__ __forceinline__ u64 ffma2(u64 a, u64 b, u64 c) {
    u64 d; asm("fma.rn.f32x2 %0, %1, %2, %3;" : "=l"(d) : "l"(a), "l"(b), "l"(c));
    return d;
}
__device__ __forceinline__ u64 add2(u64 a, u64 b) {
    u64 d; asm("add.rn.f32x2 %0, %1, %2;" : "=l"(d) : "l"(a), "l"(b));
    return d;
}

__global__ __launch_bounds__(256, 4) void cost_volume_kernel(
    const float* __restrict__ fref,
    const float* __restrict__ fls,
    const float* __restrict__ frs,
    const float* __restrict__ dinit,
    float* __restrict__ out)
{
    __shared__ float sL[CPG][RW];
    __shared__ float sR[CPG][RW];
    __shared__ float sF[CPG][256];

    const int bid = blockIdx.x;          // B*H*G = 8192 blocks
    const int g = bid & 7;
    const int h = (bid >> 3) & 255;
    const int b = bid >> 11;
    const int tid = threadIdx.x;
    const int w = tid;

    // ---- Stage rows into SMEM ----
    // Zero the halos: L/R rows, entries [0..3] and [260..267] (12 each).
    if (tid < 96) {
        const int r  = tid / 12;               // 0..7 : (arr, ci)
        const int e  = tid % 12;
        const int off = (e < 4) ? e : (256 + e);
        float (*A)[RW] = (r & 1) ? sR : sL;
        A[r >> 1][off] = 0.0f;
    }

    // Main data: 12 rows x 64 float4 = 768 float4, 3 per thread.
    {
        const int rowg0 = b * Cn * HW + g * CPG * HW + h * 256;
        #pragma unroll
        for (int k = 0; k < 3; k++) {
            const int j     = tid + (k << 8);
            const int which = j >> 6;          // 0..11
            const int col4  = j & 63;
            const int ci    = which & 3;
            const int arr   = which >> 2;      // 0=L 1=R 2=F
            const float* src = (arr == 0) ? fls : (arr == 1) ? frs : fref;
            const float4 v = __ldg((const float4*)(src + rowg0 + ci * HW) + col4);
            if (arr == 0)      *(float4*)&sL[ci][4 + (col4 << 2)] = v;
            else if (arr == 1) *(float4*)&sR[ci][4 + (col4 << 2)] = v;
            else               *(float4*)&sF[ci][col4 << 2] = v;
        }
    }

    const float disp = __ldg(dinit + b * HW + h * 256 + w);
    const float wf = (float)w;

    // Left taps n_l..n_l+2, n_l = floor(x_l at d=0); x_l increases with d.
    const float xl0 = wf + disp - 0.4f;
    const float fll = floorf(xl0);
    const int   n_l = (int)fll;
    const float tl0 = xl0 - fll - 1.0f;
    // Right taps n_r..n_r+2, n_r = floor(x_r at d=8); x_r decreases with d.
    const float xr0 = wf - disp + 0.4f;
    const float flr = floorf(xr0 - 0.8f);
    const int   n_r = (int)flr;
    const float tr0 = xr0 - flr - 1.0f;

    const u64 t02   = pk(tl0, tr0);
    const u64 step2 = pk(0.1f, -0.1f);
    const u64 amask = 0x7FFFFFFF7FFFFFFFull;

    __syncthreads();

    // ---- Gather taps from SMEM, build packed operands ----
    u64 P1[CPG], Sv[CPG], Dd[CPG], Fb[CPG];
    float sFg = 0.0f;
    const int il = n_l + 4;    // halo offset (disp in [0,1) => n_l in {w-1,w})
    const int ir = n_r + 4;    //                 n_r in {w-2,w-1}

    #pragma unroll
    for (int ci = 0; ci < CPG; ci++) {
        const float L0 = sL[ci][il],     L1 = sL[ci][il + 1], L2 = sL[ci][il + 2];
        const float R0 = sR[ci][ir],     R1 = sR[ci][ir + 1], R2 = sR[ci][ir + 2];
        const float F  = sF[ci][w];

        P1[ci] = pk(L1, R1);
        Sv[ci] = pk(0.5f * (L2 - L0), 0.5f * (R2 - R0));
        Dd[ci] = pk(fmaf(0.5f, L2 + L0, -L1), fmaf(0.5f, R2 + R0, -R1));
        Fb[ci] = pk(F, F);
        sFg = fmaf(F, F, sFg);
    }

    float* outp = out + b * (Gn * Dn * HW) + g * Dn * HW + h * 256 + w;
    const float c18 = 1.0f / 18.0f;

    u64 t2 = t02;
    #pragma unroll
    for (int d = 0; d < 9; d++) {
        const u64 at2 = t2 & amask;            // (|t_l|, |t_r|)

        u64 acc2 = 0ull, accF = 0ull;
        float ax = 0.0f;
        #pragma unroll
        for (int ci = 0; ci < CPG; ci++) {
            const u64 lw = ffma2(t2, Sv[ci],
                           ffma2(at2, Dd[ci], P1[ci]));
            acc2 = ffma2(lw, lw, acc2);        // (S wl^2, S wr^2)
            accF = ffma2(Fb[ci], lw, accF);    // (S F wl, S F wr)
            float wl, wr; upk(wl, wr, lw);
            ax = fmaf(wl, wr, ax);             // S wl*wr
        }
        t2 = add2(t2, step2);

        float a2l, a2r; upk(a2l, a2r, acc2);
        float aFl, aFr; upk(aFl, aFr, accF);
        const float hq = (a2l + a2r) + (sFg - ax);
        const float hf = aFl + aFr;
        __stcg(outp + d * HW, (hq - hf) * c18);
    }
}

extern "C" void kernel_launch(void* const* d_in, const int* in_sizes, int n_in,
                              void* d_out, int out_size)
{
    const float* fref  = (const float*)d_in[0];
    const float* fls   = (const float*)d_in[1];
    const float* frs   = (const float*)d_in[2];
    const float* dinit = (const float*)d_in[3];
    float* out = (float*)d_out;

    // blocks over (b, h, g): 4 * 256 * 8 = 8192
    cost_volume_kernel<<<Bn * 256 * Gn, 256>>>(fref, fls, frs, dinit, out);
}

// round 8
// speedup vs baseline: 1.4792x; 1.2473x over previous
#include <cuda_runtime.h>

// Cost volume s2: B=4, C=32, H=W=256, D=9, 8 groups of 4 channels.
// y-offset 0 -> 1D lerp in x; res span 0.8 < 1 px -> 3 taps/side cover all d.
// F folded into the lerp: a = wl-F = (P1-F) + t*S + |t|*Dd  (same S, Dd).
// Pairwise variance: cost = (1/18) * Sum_ci( a^2 + b^2 - a*b ),  b = wr-F.
// Inner body: 4 issue slots per (d,channel), 3 of them packed f32x2.
// Block = one (b, row h, group PAIR): rows staged in SMEM via coalesced
// float4 loads; taps gathered via LDS; zero halo = zero padding (no preds).

typedef unsigned long long u64;

constexpr int Wd = 256, Cn = 32, Bn = 4, Dn = 9, Gn = 8, CPG = 4;
constexpr int HW = 256 * 256;
constexpr int RW = 268;          // padded SMEM row: 4 halo + 256 + 8 halo
constexpr int GPB = 2;           // groups per block
constexpr int CB  = GPB * CPG;   // 8 channels staged per block

__device__ __forceinline__ u64 pk(float a, float b) {
    u64 r; asm("mov.b64 %0, {%1, %2};" : "=l"(r) : "f"(a), "f"(b)); return r;
}
__device__ __forceinline__ void upk(float& a, float& b, u64 v) {
    asm("mov.b64 {%0, %1}, %2;" : "=f"(a), "=f"(b) : "l"(v));
}
__device__ __forceinline__ u64 ffma2(u64 a, u64 b, u64 c) {
    u64 d; asm("fma.rn.f32x2 %0, %1, %2, %3;" : "=l"(d) : "l"(a), "l"(b), "l"(c));
    return d;
}
__device__ __forceinline__ u64 add2(u64 a, u64 b) {
    u64 d; asm("add.rn.f32x2 %0, %1, %2;" : "=l"(d) : "l"(a), "l"(b));
    return d;
}

__global__ __launch_bounds__(256, 4) void cost_volume_kernel(
    const float* __restrict__ fref,
    const float* __restrict__ fls,
    const float* __restrict__ frs,
    const float* __restrict__ dinit,
    float* __restrict__ out)
{
    __shared__ float sL[CB][RW];
    __shared__ float sR[CB][RW];
    __shared__ float sF[CB][256];

    const int bid = blockIdx.x;          // B*H*(G/2) = 4096 blocks
    const int gp = bid & 3;              // group pair 0..3
    const int h  = (bid >> 2) & 255;
    const int b  = bid >> 10;
    const int tid = threadIdx.x;
    const int w = tid;

    // ---- Zero halos: 16 rows (8 L + 8 R) x 12 entries ----
    if (tid < 192) {
        const int r   = tid / 12;              // 0..15 : (ci8, arr)
        const int e   = tid % 12;
        const int off = (e < 4) ? e : (256 + e);
        float (*A)[RW] = (r & 1) ? sR : sL;
        A[r >> 1][off] = 0.0f;
    }

    // ---- Stage 24 rows (8ch x {L,R,F}) as 1536 float4, 6 per thread ----
    {
        const int rowg0 = b * Cn * HW + gp * CB * HW + h * 256;
        #pragma unroll
        for (int k = 0; k < 6; k++) {
            const int j     = tid + (k << 8);
            const int which = j >> 6;          // 0..23
            const int col4  = j & 63;
            const int ci8   = which & 7;
            const int arr   = which >> 3;      // 0=L 1=R 2=F
            const float* src = (arr == 0) ? fls : (arr == 1) ? frs : fref;
            const float4 v = __ldg((const float4*)(src + rowg0 + ci8 * HW) + col4);
            if (arr == 0)      *(float4*)&sL[ci8][4 + (col4 << 2)] = v;
            else if (arr == 1) *(float4*)&sR[ci8][4 + (col4 << 2)] = v;
            else               *(float4*)&sF[ci8][col4 << 2] = v;
        }
    }

    const float disp = __ldg(dinit + b * HW + h * 256 + w);
    const float wf = (float)w;

    // Left taps n_l..n_l+2, n_l = floor(x_l at d=0); x_l increases with d.
    const float xl0 = wf + disp - 0.4f;
    const float fll = floorf(xl0);
    const int   n_l = (int)fll;
    const float tl0 = xl0 - fll - 1.0f;
    // Right taps n_r..n_r+2, n_r = floor(x_r at d=8); x_r decreases with d.
    const float xr0 = wf - disp + 0.4f;
    const float flr = floorf(xr0 - 0.8f);
    const int   n_r = (int)flr;
    const float tr0 = xr0 - flr - 1.0f;

    const u64 t02   = pk(tl0, tr0);
    const u64 step2 = pk(0.1f, -0.1f);
    const u64 amask = 0x7FFFFFFF7FFFFFFFull;
    const int il = n_l + 4;
    const int ir = n_r + 4;
    const float c18 = 1.0f / 18.0f;

    __syncthreads();

    float* outbh = out + b * (Gn * Dn * HW) + gp * GPB * Dn * HW + h * 256 + w;

    #pragma unroll
    for (int gg = 0; gg < GPB; gg++) {
        // ---- Gather taps, build packed operands (F pre-subtracted) ----
        u64 P1F[CPG], Sv[CPG], Dd[CPG];
        #pragma unroll
        for (int ci = 0; ci < CPG; ci++) {
            const int c8 = gg * CPG + ci;
            const float L0 = sL[c8][il], L1 = sL[c8][il + 1], L2 = sL[c8][il + 2];
            const float R0 = sR[c8][ir], R1 = sR[c8][ir + 1], R2 = sR[c8][ir + 2];
            const float F  = sF[c8][w];

            P1F[ci] = pk(L1 - F, R1 - F);
            Sv[ci]  = pk(0.5f * (L2 - L0), 0.5f * (R2 - R0));
            Dd[ci]  = pk(fmaf(0.5f, L2 + L0, -L1), fmaf(0.5f, R2 + R0, -R1));
        }

        float* outp = outbh + gg * Dn * HW;
        u64 t2 = t02;

        #pragma unroll
        for (int d = 0; d < 9; d++) {
            const u64 at2 = t2 & amask;        // (|t_l|, |t_r|)

            u64 accP = 0ull;
            float ax = 0.0f;
            #pragma unroll
            for (int ci = 0; ci < CPG; ci++) {
                const u64 lw = ffma2(t2, Sv[ci],
                               ffma2(at2, Dd[ci], P1F[ci]));
                accP = ffma2(lw, lw, accP);    // (S a^2, S b^2)
                float a, bb; upk(a, bb, lw);
                ax = fmaf(a, bb, ax);          // S a*b
            }
            t2 = add2(t2, step2);

            float aPl, aPr; upk(aPl, aPr, accP);
            __stcg(outp + d * HW, ((aPl + aPr) - ax) * c18);
        }
    }
}

extern "C" void kernel_launch(void* const* d_in, const int* in_sizes, int n_in,
                              void* d_out, int out_size)
{
    const float* fref  = (const float*)d_in[0];
    const float* fls   = (const float*)d_in[1];
    const float* frs   = (const float*)d_in[2];
    const float* dinit = (const float*)d_in[3];
    float* out = (float*)d_out;

    // blocks over (b, h, group-pair): 4 * 256 * 4 = 4096
    cost_volume_kernel<<<Bn * 256 * (Gn / GPB), 256>>>(fref, fls, frs, dinit, out);
}